// round 16
// baseline (speedup 1.0000x reference)
#include <cuda_runtime.h>
#include <cuda_fp16.h>
#include <cstdint>

#define BATCH 4
#define DIMC 96
#define HEADS 3
#define NBH 12
#define WSQ 49
#define QK_SCALE 0.17677669529663687f

// ---- k2 geometry: 16x16 px tile ----
#define PXB 144
#define HXL 22
#define HALO_PX 484                  // 22*22
#define HALO_BYTES (HALO_PX * PXB)   // 69696
#define SMEM_K2 HALO_BYTES
#define BTAPU2 896                   // uint2 per tap: 4 ks * 7 nt * 32 lanes
// epilogue overlay: attn [0,51200), inv [51200,52224), v [52224,69120)
#define ATTN_OFF 0
#define INV_OFF  51200
#define VSH_OFF  52224

// ---- k1/k3 geometry (fp16) ----
#define XSTR 104
#define SMEM_G (128 * XSTR * 2)      // 26624 B
#define NQKVF (36 * 6 * 32)
#define NPROJF (12 * 6 * 32)

// ---------------- scratch (device globals) ----------------
__device__ __half g_qkh[(size_t)NBH * 128 * 128 * 64];
__device__ float  g_v  [(size_t)NBH * 32 * 128 * 128];
__device__ float  g_att[(size_t)BATCH * DIMC * 128 * 128];
__device__ uint2  g_w2f[(size_t)WSQ * BTAPU2];
__device__ uint2  g_wqkv[NQKVF];
__device__ uint2  g_wproj[NPROJF];

__device__ __forceinline__ void mma_f16_16n8k16(float* acc, const uint32_t* a, uint32_t bx, uint32_t by) {
    asm volatile(
        "mma.sync.aligned.m16n8k16.row.col.f32.f16.f16.f32 "
        "{%0,%1,%2,%3},{%4,%5,%6,%7},{%8,%9},{%0,%1,%2,%3};"
        : "+f"(acc[0]), "+f"(acc[1]), "+f"(acc[2]), "+f"(acc[3])
        : "r"(a[0]), "r"(a[1]), "r"(a[2]), "r"(a[3]), "r"(bx), "r"(by));
}

__device__ __forceinline__ uint32_t pack_h2(float lo, float hi) {
    __half2 h = __floats2half2_rn(lo, hi);
    return *(uint32_t*)&h;
}

// ---------------- dummy: keeps ncu capture index on k2 ----------------------
__global__ void k_dummy() {}

// ---------------- K0: pack all weight fragments -----------------------------
__global__ void k0_prep(const float* __restrict__ attn_w,
                        const float* __restrict__ qkv_w,
                        const float* __restrict__ proj_w) {
    int idx = blockIdx.x * 256 + threadIdx.x;
    if (idx < WSQ * BTAPU2) {
        int lane = idx & 31;
        int nt   = (idx >> 5) % 7;
        int ks   = ((idx >> 5) / 7) & 3;
        int s    = idx / (32 * 28);
        int n = nt * 8 + (lane >> 2);
        int k0 = ks * 16 + (lane & 3) * 2;
        uint2 u;
        u.x = (n < WSQ) ? pack_h2(attn_w[(n * 64 + k0) * WSQ + s],
                                  attn_w[(n * 64 + k0 + 1) * WSQ + s]) : 0u;
        u.y = (n < WSQ) ? pack_h2(attn_w[(n * 64 + k0 + 8) * WSQ + s],
                                  attn_w[(n * 64 + k0 + 9) * WSQ + s]) : 0u;
        g_w2f[idx] = u;
        return;
    }
    int i = idx - WSQ * BTAPU2;
    if (i < NQKVF) {
        int lane = i & 31, r = i >> 5;
        int ks = r % 6, nt = r / 6;
        int oc = nt * 8 + (lane >> 2);
        int k  = ks * 16 + (lane & 3) * 2;
        uint2 u;
        u.x = pack_h2(qkv_w[oc * 96 + k],     qkv_w[oc * 96 + k + 1]);
        u.y = pack_h2(qkv_w[oc * 96 + k + 8], qkv_w[oc * 96 + k + 9]);
        g_wqkv[i] = u;
        return;
    }
    i -= NQKVF;
    if (i < NPROJF) {
        int lane = i & 31, r = i >> 5;
        int ks = r % 6, nt = r / 6;
        int oc = nt * 8 + (lane >> 2);
        int k  = ks * 16 + (lane & 3) * 2;
        uint2 u;
        u.x = pack_h2(proj_w[oc * 96 + k],     proj_w[oc * 96 + k + 1]);
        u.y = pack_h2(proj_w[oc * 96 + k + 8], proj_w[oc * 96 + k + 9]);
        g_wproj[i] = u;
    }
}

// ---------------- K1: 1x1 qkv conv via fp16 mma -----------------------------
__global__ __launch_bounds__(256, 4) void k1_qkv(const float* __restrict__ x,
                                                 const float* __restrict__ bias) {
    extern __shared__ char smemc[];
    __half* xs = (__half*)smemc;
    const int tid = threadIdx.x, lane = tid & 31, wid = tid >> 5;
    const int row = blockIdx.x, b = blockIdx.y;

    const float4* xb = (const float4*)(x + (((size_t)b * DIMC) << 14) + (row << 7));
    #pragma unroll
    for (int it = 0; it < 12; ++it) {
        int idx = tid + it * 256;
        int c = idx >> 5, p4 = idx & 31;
        float4 v = xb[(size_t)c * 4096 + p4];
        int px0 = p4 * 4;
        xs[(px0 + 0) * XSTR + c] = __float2half(v.x);
        xs[(px0 + 1) * XSTR + c] = __float2half(v.y);
        xs[(px0 + 2) * XSTR + c] = __float2half(v.z);
        xs[(px0 + 3) * XSTR + c] = __float2half(v.w);
    }
    __syncthreads();

    const int pr = wid * 16 + (lane >> 2);
    const int c0 = (lane & 3) * 2;
    uint32_t A[6][4];
    #pragma unroll
    for (int ks = 0; ks < 6; ++ks) {
        int kb = ks * 16 + c0;
        A[ks][0] = *(const uint32_t*)&xs[pr * XSTR + kb];
        A[ks][1] = *(const uint32_t*)&xs[(pr + 8) * XSTR + kb];
        A[ks][2] = *(const uint32_t*)&xs[pr * XSTR + kb + 8];
        A[ks][3] = *(const uint32_t*)&xs[(pr + 8) * XSTR + kb + 8];
    }

    const int bh_base = b * HEADS;
    for (int nt = 0; nt < 36; ++nt) {
        uint2 bf[6];
        #pragma unroll
        for (int ks = 0; ks < 6; ++ks) bf[ks] = g_wqkv[(nt * 6 + ks) * 32 + lane];
        float acc[4] = {0.f, 0.f, 0.f, 0.f};
        #pragma unroll
        for (int ks = 0; ks < 6; ++ks) mma_f16_16n8k16(acc, A[ks], bf[ks].x, bf[ks].y);

        int oc = nt * 8 + ((lane & 3) << 1);
        float b0 = bias[oc], b1 = bias[oc + 1];
        if (nt < 24) {
            int oc96 = oc - (nt < 12 ? 0 : 96);
            int head = oc96 >> 5, ch = (oc96 & 31) + (nt < 12 ? 0 : 32);
            size_t base = ((((size_t)(bh_base + head) * 128 + row) << 7));
            float s = (nt < 12) ? QK_SCALE : 1.0f;
            #pragma unroll
            for (int i = 0; i < 2; ++i) {
                int px = pr + i * 8;
                __half2 h = __floats2half2_rn((acc[2 * i] + b0) * s, (acc[2 * i + 1] + b1) * s);
                *(__half2*)&g_qkh[(base + px) * 64 + ch] = h;
            }
        } else {
            int oc96 = oc - 192;
            int head = oc96 >> 5, ch = oc96 & 31;
            float* vb = g_v + ((((size_t)(bh_base + head) * 32) + ch) << 14) + (row << 7);
            #pragma unroll
            for (int i = 0; i < 2; ++i) {
                int px = pr + i * 8;
                vb[px]             = acc[2 * i] + b0;
                vb[(1 << 14) + px] = acc[2 * i + 1] + b1;
            }
        }
    }
}

// ---------------- K2 v6: 16x16 tile, 2mt x 7nt per warp, occupancy 3 --------
// Same B-traffic-per-pixel as R9 (2 mtiles/warp), but halo 69.7KB -> 3 blk/SM.
// Softmax in smem (no lg[49] regs); nt B-loads split 4+3 to cap liveness.
__global__ __launch_bounds__(256, 3) void k2_attn(const float* __restrict__ attn_b) {
    extern __shared__ char smemk2[];
    float* attn_sh = (float*)(smemk2 + ATTN_OFF);   // [256][50]
    float* inv_sh  = (float*)(smemk2 + INV_OFF);    // [256]
    float* v_sh    = (float*)(smemk2 + VSH_OFF);    // [22][24][8]

    const int tid = threadIdx.x;
    const int lane = tid & 31, wid = tid >> 5;
    const int bh  = blockIdx.z;
    const int ty0 = blockIdx.y * 16;
    const int tx0 = blockIdx.x * 16;

    uint32_t sb;
    { uint64_t t_; asm("cvta.to.shared.u64 %0, %1;" : "=l"(t_) : "l"(smemk2)); sb = (uint32_t)t_; }

    // ---- load qk halo (22 x 22 px, 144 B/px) ----
    const uint4* qk4 = (const uint4*)g_qkh;
    for (int idx = tid; idx < HALO_PX * 8; idx += 256) {
        int pxi = idx >> 3, g = idx & 7;
        int hy = pxi / HXL, hx = pxi - hy * HXL;
        int gy = ty0 - 3 + hy, gx = tx0 - 3 + hx;
        uint4 val = make_uint4(0, 0, 0, 0);
        if ((unsigned)gy < 128u && (unsigned)gx < 128u)
            val = qk4[((((size_t)bh * 128 + gy) << 7) + gx) * 8 + g];
        *(uint4*)(smemk2 + pxi * PXB + g * 16) = val;
    }
    __syncthreads();

    // warp w owns pixel-rows {2w, 2w+1}; mtile m -> row 2w+m (16 px)
    uint32_t abase[2];
    #pragma unroll
    for (int m = 0; m < 2; ++m) {
        int row = 2 * wid + m;
        abase[m] = sb + (uint32_t)(row * HXL + (lane & 15)) * PXB + (lane >> 4) * 16;
    }

    float acc[2][7][4];
    #pragma unroll
    for (int m = 0; m < 2; ++m)
        #pragma unroll
        for (int nt = 0; nt < 7; ++nt)
            #pragma unroll
            for (int e = 0; e < 4; ++e) acc[m][nt][e] = 0.0f;

    const uint2* wbase = g_w2f + lane;
    #pragma unroll 1
    for (int s = 0; s < WSQ; ++s) {
        int dy = s / 7, dx = s - dy * 7;
        uint32_t toff = (uint32_t)(dy * HXL + dx) * PXB;
        const uint2* wtap = wbase + (size_t)s * BTAPU2;
        #pragma unroll
        for (int ks = 0; ks < 4; ++ks) {
            uint32_t a[2][4];
            #pragma unroll
            for (int m = 0; m < 2; ++m) {
                asm volatile("ldmatrix.sync.aligned.m8n8.x4.shared.b16 {%0,%1,%2,%3}, [%4];"
                    : "=r"(a[m][0]), "=r"(a[m][1]), "=r"(a[m][2]), "=r"(a[m][3])
                    : "r"(abase[m] + toff + ks * 32));
            }
            // nt 0..3
            {
                uint2 bf[4];
                #pragma unroll
                for (int nt = 0; nt < 4; ++nt) bf[nt] = __ldg(wtap + (ks * 7 + nt) * 32);
                #pragma unroll
                for (int nt = 0; nt < 4; ++nt) {
                    mma_f16_16n8k16(acc[0][nt], a[0], bf[nt].x, bf[nt].y);
                    mma_f16_16n8k16(acc[1][nt], a[1], bf[nt].x, bf[nt].y);
                }
            }
            // nt 4..6
            {
                uint2 bf[3];
                #pragma unroll
                for (int j = 0; j < 3; ++j) bf[j] = __ldg(wtap + (ks * 7 + 4 + j) * 32);
                #pragma unroll
                for (int j = 0; j < 3; ++j) {
                    mma_f16_16n8k16(acc[0][4 + j], a[0], bf[j].x, bf[j].y);
                    mma_f16_16n8k16(acc[1][4 + j], a[1], bf[j].x, bf[j].y);
                }
            }
        }
    }

    __syncthreads();   // halo reads done -> smem becomes attn buffer

    // ---- logits (+bias) to smem ----
    #pragma unroll
    for (int m = 0; m < 2; ++m) {
        int p0 = (2 * wid + m) * 16 + (lane >> 2);
        #pragma unroll
        for (int nt = 0; nt < 7; ++nt) {
            int t0 = nt * 8 + (lane & 3) * 2;
            if (t0 < WSQ) {
                float bb = attn_b[t0];
                attn_sh[p0 * 50 + t0]       = acc[m][nt][0] + bb;
                attn_sh[(p0 + 8) * 50 + t0] = acc[m][nt][2] + bb;
            }
            if (t0 + 1 < WSQ) {
                float bb = attn_b[t0 + 1];
                attn_sh[p0 * 50 + t0 + 1]       = acc[m][nt][1] + bb;
                attn_sh[(p0 + 8) * 50 + t0 + 1] = acc[m][nt][3] + bb;
            }
        }
    }
    __syncthreads();

    // ---- softmax in smem: thread tid owns pixel tid ----
    {
        float mx = -1e30f;
        #pragma unroll
        for (int t = 0; t < WSQ; ++t) mx = fmaxf(mx, attn_sh[tid * 50 + t]);
        float sum = 0.0f;
        #pragma unroll
        for (int t = 0; t < WSQ; ++t) {
            float e = __expf(attn_sh[tid * 50 + t] - mx);
            attn_sh[tid * 50 + t] = e;
            sum += e;
        }
        inv_sh[tid] = 1.0f / sum;
    }

    const int b    = bh / HEADS;
    const int head = bh - b * HEADS;
    const int py = tid >> 4, px = tid & 15;

    // ---- attn . V (4 chunks of 8 ch) ----
    for (int vcblk = 0; vcblk < 4; ++vcblk) {
        __syncthreads();   // first iter also publishes softmax
        for (int idx = tid; idx < 8 * HALO_PX; idx += 256) {
            int cc = idx / HALO_PX;
            int rr = idx - cc * HALO_PX;
            int hy = rr / HXL, hx = rr - hy * HXL;
            int gyy = ty0 - 3 + hy, gxx = tx0 - 3 + hx;
            float val = 0.0f;
            if ((unsigned)gyy < 128u && (unsigned)gxx < 128u)
                val = g_v[((((size_t)bh * 32) + vcblk * 8 + cc) << 14) + (gyy << 7) + gxx];
            v_sh[(hy * 24 + hx) * 8 + cc] = val;
        }
        __syncthreads();

        float o[8];
        #pragma unroll
        for (int vc = 0; vc < 8; ++vc) o[vc] = 0.0f;
        const float* arow = attn_sh + tid * 50;
        #pragma unroll
        for (int dy = 0; dy < 7; ++dy) {
            #pragma unroll
            for (int dx = 0; dx < 7; ++dx) {
                float a = arow[dy * 7 + dx];
                const float4* vp = (const float4*)&v_sh[((py + dy) * 24 + px + dx) * 8];
                float4 v0 = vp[0], v1 = vp[1];
                o[0] = fmaf(a, v0.x, o[0]); o[1] = fmaf(a, v0.y, o[1]);
                o[2] = fmaf(a, v0.z, o[2]); o[3] = fmaf(a, v0.w, o[3]);
                o[4] = fmaf(a, v1.x, o[4]); o[5] = fmaf(a, v1.y, o[5]);
                o[6] = fmaf(a, v1.z, o[6]); o[7] = fmaf(a, v1.w, o[7]);
            }
        }
        float inv = inv_sh[tid];
        #pragma unroll
        for (int vc = 0; vc < 8; ++vc)
            g_att[((((size_t)b * DIMC) + head * 32 + vcblk * 8 + vc) << 14)
                  + ((ty0 + py) << 7) + (tx0 + px)] = o[vc] * inv;
    }
}

// ---------------- K3: 1x1 proj via fp16 mma -> d_out ------------------------
__global__ __launch_bounds__(256, 4) void k3_proj(const float* __restrict__ bias,
                                                  float* __restrict__ out) {
    extern __shared__ char smemc[];
    __half* xs = (__half*)smemc;
    const int tid = threadIdx.x, lane = tid & 31, wid = tid >> 5;
    const int row = blockIdx.x, b = blockIdx.y;

    const float4* xb = (const float4*)(g_att + (((size_t)b * DIMC) << 14) + (row << 7));
    #pragma unroll
    for (int it = 0; it < 12; ++it) {
        int idx = tid + it * 256;
        int c = idx >> 5, p4 = idx & 31;
        float4 v = xb[(size_t)c * 4096 + p4];
        int px0 = p4 * 4;
        xs[(px0 + 0) * XSTR + c] = __float2half(v.x);
        xs[(px0 + 1) * XSTR + c] = __float2half(v.y);
        xs[(px0 + 2) * XSTR + c] = __float2half(v.z);
        xs[(px0 + 3) * XSTR + c] = __float2half(v.w);
    }
    __syncthreads();

    const int pr = wid * 16 + (lane >> 2);
    const int c0 = (lane & 3) * 2;
    uint32_t A[6][4];
    #pragma unroll
    for (int ks = 0; ks < 6; ++ks) {
        int kb = ks * 16 + c0;
        A[ks][0] = *(const uint32_t*)&xs[pr * XSTR + kb];
        A[ks][1] = *(const uint32_t*)&xs[(pr + 8) * XSTR + kb];
        A[ks][2] = *(const uint32_t*)&xs[pr * XSTR + kb + 8];
        A[ks][3] = *(const uint32_t*)&xs[(pr + 8) * XSTR + kb + 8];
    }

    for (int nt = 0; nt < 12; ++nt) {
        uint2 bf[6];
        #pragma unroll
        for (int ks = 0; ks < 6; ++ks) bf[ks] = g_wproj[(nt * 6 + ks) * 32 + lane];
        float acc[4] = {0.f, 0.f, 0.f, 0.f};
        #pragma unroll
        for (int ks = 0; ks < 6; ++ks) mma_f16_16n8k16(acc, A[ks], bf[ks].x, bf[ks].y);

        int oc = nt * 8 + ((lane & 3) << 1);
        float b0 = bias[oc], b1 = bias[oc + 1];
        float* ob = out + ((((size_t)b * DIMC) + oc) << 14) + (row << 7);
        #pragma unroll
        for (int i = 0; i < 2; ++i) {
            int px = pr + i * 8;
            ob[px]             = acc[2 * i] + b0;
            ob[(1 << 14) + px] = acc[2 * i + 1] + b1;
        }
    }
}

// ---------------- launch ---------------------------------------------------
extern "C" void kernel_launch(void* const* d_in, const int* in_sizes, int n_in,
                              void* d_out, int out_size) {
    const float* x      = (const float*)d_in[0];
    const float* qkv_w  = (const float*)d_in[1];
    const float* qkv_b  = (const float*)d_in[2];
    const float* attn_w = (const float*)d_in[3];
    const float* attn_b = (const float*)d_in[4];
    const float* proj_w = (const float*)d_in[5];
    const float* proj_b = (const float*)d_in[6];
    float* out = (float*)d_out;

    cudaFuncSetAttribute(k1_qkv,  cudaFuncAttributeMaxDynamicSharedMemorySize, SMEM_G);
    cudaFuncSetAttribute(k2_attn, cudaFuncAttributeMaxDynamicSharedMemorySize, SMEM_K2);
    cudaFuncSetAttribute(k3_proj, cudaFuncAttributeMaxDynamicSharedMemorySize, SMEM_G);

    k_dummy<<<1, 32>>>();   // keep ncu capture index on k2
    const int k0n = WSQ * BTAPU2 + NQKVF + NPROJF;
    k0_prep<<<(k0n + 255) / 256, 256>>>(attn_w, qkv_w, proj_w);
    k1_qkv<<<dim3(128, BATCH), 256, SMEM_G>>>(x, qkv_b);
    k2_attn<<<dim3(8, 8, NBH), 256, SMEM_K2>>>(attn_b);
    k3_proj<<<dim3(128, BATCH), 256, SMEM_G>>>(proj_b, out);
}

// round 17
// speedup vs baseline: 1.2254x; 1.2254x over previous
#include <cuda_runtime.h>
#include <cuda_fp16.h>
#include <cstdint>

#define BATCH 4
#define DIMC 96
#define HEADS 3
#define NBH 12
#define WSQ 49
#define QK_SCALE 0.17677669529663687f

// ---- k2 geometry (R9/R11) ----
#define PXB 144
#define HALO_PX 532
#define HALO_BYTES (HALO_PX * PXB)   // 76608
#define BTAPU2 896                   // uint2 per tap: 4 ks * 7 nt * 32 lanes
#define SMEM_K2 HALO_BYTES           // epilogue overlay fits (69120)
#define HALO_N 532

// ---- k1/k3 geometry (fp16) ----
#define XSTR 104
#define SMEM_G (128 * XSTR * 2)      // 26624 B
#define NQKVF (36 * 6 * 32)
#define NPROJF (12 * 6 * 32)

// ---------------- scratch (device globals) ----------------
__device__ __half g_qkh[(size_t)NBH * 128 * 128 * 64];
__device__ float  g_v  [(size_t)NBH * 32 * 128 * 128];
__device__ float  g_att[(size_t)BATCH * DIMC * 128 * 128];
__device__ uint2  g_w2f[(size_t)WSQ * BTAPU2];
__device__ uint2  g_wqkv[NQKVF];
__device__ uint2  g_wproj[NPROJF];

__device__ __forceinline__ void mma_f16_16n8k16(float* acc, const uint32_t* a, uint32_t bx, uint32_t by) {
    asm volatile(
        "mma.sync.aligned.m16n8k16.row.col.f32.f16.f16.f32 "
        "{%0,%1,%2,%3},{%4,%5,%6,%7},{%8,%9},{%0,%1,%2,%3};"
        : "+f"(acc[0]), "+f"(acc[1]), "+f"(acc[2]), "+f"(acc[3])
        : "r"(a[0]), "r"(a[1]), "r"(a[2]), "r"(a[3]), "r"(bx), "r"(by));
}

__device__ __forceinline__ uint32_t pack_h2(float lo, float hi) {
    __half2 h = __floats2half2_rn(lo, hi);
    return *(uint32_t*)&h;
}

// ---------------- K0: pack all weight fragments (all fp16) -----------------
__global__ void k0_prep(const float* __restrict__ attn_w,
                        const float* __restrict__ qkv_w,
                        const float* __restrict__ proj_w) {
    int idx = blockIdx.x * 256 + threadIdx.x;
    if (idx < WSQ * BTAPU2) {
        int lane = idx & 31;
        int nt   = (idx >> 5) % 7;
        int ks   = ((idx >> 5) / 7) & 3;
        int s    = idx / (32 * 28);
        int n = nt * 8 + (lane >> 2);
        int k0 = ks * 16 + (lane & 3) * 2;
        uint2 u;
        u.x = (n < WSQ) ? pack_h2(attn_w[(n * 64 + k0) * WSQ + s],
                                  attn_w[(n * 64 + k0 + 1) * WSQ + s]) : 0u;
        u.y = (n < WSQ) ? pack_h2(attn_w[(n * 64 + k0 + 8) * WSQ + s],
                                  attn_w[(n * 64 + k0 + 9) * WSQ + s]) : 0u;
        g_w2f[idx] = u;
        return;
    }
    int i = idx - WSQ * BTAPU2;
    if (i < NQKVF) {
        int lane = i & 31, r = i >> 5;
        int ks = r % 6, nt = r / 6;
        int oc = nt * 8 + (lane >> 2);
        int k  = ks * 16 + (lane & 3) * 2;
        uint2 u;
        u.x = pack_h2(qkv_w[oc * 96 + k],     qkv_w[oc * 96 + k + 1]);
        u.y = pack_h2(qkv_w[oc * 96 + k + 8], qkv_w[oc * 96 + k + 9]);
        g_wqkv[i] = u;
        return;
    }
    i -= NQKVF;
    if (i < NPROJF) {
        int lane = i & 31, r = i >> 5;
        int ks = r % 6, nt = r / 6;
        int oc = nt * 8 + (lane >> 2);
        int k  = ks * 16 + (lane & 3) * 2;
        uint2 u;
        u.x = pack_h2(proj_w[oc * 96 + k],     proj_w[oc * 96 + k + 1]);
        u.y = pack_h2(proj_w[oc * 96 + k + 8], proj_w[oc * 96 + k + 9]);
        g_wproj[i] = u;
    }
}

// ---------------- K1: 1x1 qkv conv via fp16 mma -----------------------------
__global__ __launch_bounds__(256, 4) void k1_qkv(const float* __restrict__ x,
                                                 const float* __restrict__ bias) {
    extern __shared__ char smemc[];
    __half* xs = (__half*)smemc;
    const int tid = threadIdx.x, lane = tid & 31, wid = tid >> 5;
    const int row = blockIdx.x, b = blockIdx.y;

    const float4* xb = (const float4*)(x + (((size_t)b * DIMC) << 14) + (row << 7));
    #pragma unroll
    for (int it = 0; it < 12; ++it) {
        int idx = tid + it * 256;
        int c = idx >> 5, p4 = idx & 31;
        float4 v = xb[(size_t)c * 4096 + p4];
        int px0 = p4 * 4;
        xs[(px0 + 0) * XSTR + c] = __float2half(v.x);
        xs[(px0 + 1) * XSTR + c] = __float2half(v.y);
        xs[(px0 + 2) * XSTR + c] = __float2half(v.z);
        xs[(px0 + 3) * XSTR + c] = __float2half(v.w);
    }
    __syncthreads();

    const int pr = wid * 16 + (lane >> 2);
    const int c0 = (lane & 3) * 2;
    uint32_t A[6][4];
    #pragma unroll
    for (int ks = 0; ks < 6; ++ks) {
        int kb = ks * 16 + c0;
        A[ks][0] = *(const uint32_t*)&xs[pr * XSTR + kb];
        A[ks][1] = *(const uint32_t*)&xs[(pr + 8) * XSTR + kb];
        A[ks][2] = *(const uint32_t*)&xs[pr * XSTR + kb + 8];
        A[ks][3] = *(const uint32_t*)&xs[(pr + 8) * XSTR + kb + 8];
    }

    const int bh_base = b * HEADS;
    for (int nt = 0; nt < 36; ++nt) {
        uint2 bf[6];
        #pragma unroll
        for (int ks = 0; ks < 6; ++ks) bf[ks] = g_wqkv[(nt * 6 + ks) * 32 + lane];
        float acc[4] = {0.f, 0.f, 0.f, 0.f};
        #pragma unroll
        for (int ks = 0; ks < 6; ++ks) mma_f16_16n8k16(acc, A[ks], bf[ks].x, bf[ks].y);

        int oc = nt * 8 + ((lane & 3) << 1);
        float b0 = bias[oc], b1 = bias[oc + 1];
        if (nt < 24) {
            int oc96 = oc - (nt < 12 ? 0 : 96);
            int head = oc96 >> 5, ch = (oc96 & 31) + (nt < 12 ? 0 : 32);
            size_t base = ((((size_t)(bh_base + head) * 128 + row) << 7));
            float s = (nt < 12) ? QK_SCALE : 1.0f;
            #pragma unroll
            for (int i = 0; i < 2; ++i) {
                int px = pr + i * 8;
                __half2 h = __floats2half2_rn((acc[2 * i] + b0) * s, (acc[2 * i + 1] + b1) * s);
                *(__half2*)&g_qkh[(base + px) * 64 + ch] = h;
            }
        } else {
            int oc96 = oc - 192;
            int head = oc96 >> 5, ch = oc96 & 31;
            float* vb = g_v + ((((size_t)(bh_base + head) * 32) + ch) << 14) + (row << 7);
            #pragma unroll
            for (int i = 0; i < 2; ++i) {
                int px = pr + i * 8;
                vb[px]             = acc[2 * i] + b0;
                vb[(1 << 14) + px] = acc[2 * i + 1] + b1;
            }
        }
    }
}

// ---------------- K2 (R11 + dy/dx nest): fp16 mma logits + softmax + AV ----
// 8 warps; warp w owns mtiles {2w,2w+1} x all 7 ntiles. B frags via __ldg.
// Tap loop = dy outer (no unroll) x dx inner (fully unrolled): ptxas can
// overlap tap dx+1's B loads with tap dx's mma block.
__global__ __launch_bounds__(256, 2) void k2_attn(const float* __restrict__ attn_b) {
    extern __shared__ char smemk2[];
    float* logits_sh = (float*)smemk2;
    float* v_sh = (float*)(smemk2 + 256 * 50 * 4);

    const int tid = threadIdx.x;
    const int lane = tid & 31, wid = tid >> 5;
    const int bh  = blockIdx.z;
    const int ty0 = blockIdx.y * 8;
    const int tx0 = blockIdx.x * 32;

    uint32_t sb;
    { uint64_t t_; asm("cvta.to.shared.u64 %0, %1;" : "=l"(t_) : "l"(smemk2)); sb = (uint32_t)t_; }

    const uint4* qk4 = (const uint4*)g_qkh;
    for (int idx = tid; idx < HALO_PX * 8; idx += 256) {
        int pxi = idx >> 3, g = idx & 7;
        int hy = pxi / 38, hx = pxi - hy * 38;
        int gy = ty0 - 3 + hy, gx = tx0 - 3 + hx;
        uint4 val = make_uint4(0, 0, 0, 0);
        if ((unsigned)gy < 128u && (unsigned)gx < 128u)
            val = qk4[((((size_t)bh * 128 + gy) << 7) + gx) * 8 + g];
        *(uint4*)(smemk2 + pxi * PXB + g * 16) = val;
    }
    __syncthreads();

    uint32_t abase[2];
    #pragma unroll
    for (int m = 0; m < 2; ++m) {
        int p = (2 * wid + m) * 16 + (lane & 15);
        abase[m] = sb + ((p >> 5) * 38 + (p & 31)) * PXB + (lane >> 4) * 16;
    }

    float acc[2][7][4];
    #pragma unroll
    for (int m = 0; m < 2; ++m)
        #pragma unroll
        for (int nt = 0; nt < 7; ++nt)
            #pragma unroll
            for (int e = 0; e < 4; ++e) acc[m][nt][e] = 0.0f;

    const uint2* wbase = g_w2f + lane;
    #pragma unroll 1
    for (int dy = 0; dy < 7; ++dy) {
        const uint32_t toffy = (uint32_t)(dy * 38) * PXB;
        const uint2* wrow = wbase + (size_t)(dy * 7) * BTAPU2;
        #pragma unroll
        for (int dx = 0; dx < 7; ++dx) {
            uint32_t toff = toffy + (uint32_t)dx * PXB;
            const uint2* wtap = wrow + (size_t)dx * BTAPU2;
            #pragma unroll
            for (int ks = 0; ks < 4; ++ks) {
                uint2 bf[7];
                #pragma unroll
                for (int nt = 0; nt < 7; ++nt) bf[nt] = __ldg(wtap + (ks * 7 + nt) * 32);
                uint32_t a[2][4];
                #pragma unroll
                for (int m = 0; m < 2; ++m) {
                    asm volatile("ldmatrix.sync.aligned.m8n8.x4.shared.b16 {%0,%1,%2,%3}, [%4];"
                        : "=r"(a[m][0]), "=r"(a[m][1]), "=r"(a[m][2]), "=r"(a[m][3])
                        : "r"(abase[m] + toff + ks * 32));
                }
                #pragma unroll
                for (int nt = 0; nt < 7; ++nt) {
                    mma_f16_16n8k16(acc[0][nt], a[0], bf[nt].x, bf[nt].y);
                    mma_f16_16n8k16(acc[1][nt], a[1], bf[nt].x, bf[nt].y);
                }
            }
        }
    }

    __syncthreads();

    #pragma unroll
    for (int m = 0; m < 2; ++m) {
        int p0 = (2 * wid + m) * 16 + (lane >> 2);
        #pragma unroll
        for (int nt = 0; nt < 7; ++nt) {
            int t0 = nt * 8 + (lane & 3) * 2;
            if (t0 < WSQ) {
                float bb = attn_b[t0];
                logits_sh[p0 * 50 + t0]       = acc[m][nt][0] + bb;
                logits_sh[(p0 + 8) * 50 + t0] = acc[m][nt][2] + bb;
            }
            if (t0 + 1 < WSQ) {
                float bb = attn_b[t0 + 1];
                logits_sh[p0 * 50 + t0 + 1]       = acc[m][nt][1] + bb;
                logits_sh[(p0 + 8) * 50 + t0 + 1] = acc[m][nt][3] + bb;
            }
        }
    }
    __syncthreads();

    const int py = tid >> 5, px = tid & 31;
    float lg[WSQ];
    float mx = -1e30f;
    #pragma unroll
    for (int t = 0; t < WSQ; ++t) { lg[t] = logits_sh[tid * 50 + t]; mx = fmaxf(mx, lg[t]); }
    float sum = 0.0f;
    #pragma unroll
    for (int t = 0; t < WSQ; ++t) { lg[t] = __expf(lg[t] - mx); sum += lg[t]; }
    float inv = 1.0f / sum;
    #pragma unroll
    for (int t = 0; t < WSQ; ++t) lg[t] *= inv;

    const int b    = bh / HEADS;
    const int head = bh - b * HEADS;

    for (int vcblk = 0; vcblk < 4; ++vcblk) {
        __syncthreads();
        for (int idx = tid; idx < 8 * HALO_N; idx += 256) {
            int cc = idx / HALO_N;
            int rr = idx - cc * HALO_N;
            int hy = rr / 38, hx = rr - hy * 38;
            int gyy = ty0 - 3 + hy, gxx = tx0 - 3 + hx;
            float val = 0.0f;
            if ((unsigned)gyy < 128u && (unsigned)gxx < 128u)
                val = g_v[((((size_t)bh * 32) + vcblk * 8 + cc) << 14) + (gyy << 7) + gxx];
            v_sh[(hy * 40 + hx) * 8 + cc] = val;
        }
        __syncthreads();

        float o[8];
        #pragma unroll
        for (int vc = 0; vc < 8; ++vc) o[vc] = 0.0f;
        #pragma unroll
        for (int dy = 0; dy < 7; ++dy) {
            #pragma unroll
            for (int dx = 0; dx < 7; ++dx) {
                float a = lg[dy * 7 + dx];
                const float4* vp = (const float4*)&v_sh[((py + dy) * 40 + px + dx) * 8];
                float4 v0 = vp[0], v1 = vp[1];
                o[0] = fmaf(a, v0.x, o[0]); o[1] = fmaf(a, v0.y, o[1]);
                o[2] = fmaf(a, v0.z, o[2]); o[3] = fmaf(a, v0.w, o[3]);
                o[4] = fmaf(a, v1.x, o[4]); o[5] = fmaf(a, v1.y, o[5]);
                o[6] = fmaf(a, v1.z, o[6]); o[7] = fmaf(a, v1.w, o[7]);
            }
        }
        #pragma unroll
        for (int vc = 0; vc < 8; ++vc)
            g_att[((((size_t)b * DIMC) + head * 32 + vcblk * 8 + vc) << 14)
                  + ((ty0 + py) << 7) + (tx0 + px)] = o[vc];
    }
}

// ---------------- K3: 1x1 proj via fp16 mma -> d_out ------------------------
__global__ __launch_bounds__(256, 4) void k3_proj(const float* __restrict__ bias,
                                                  float* __restrict__ out) {
    extern __shared__ char smemc[];
    __half* xs = (__half*)smemc;
    const int tid = threadIdx.x, lane = tid & 31, wid = tid >> 5;
    const int row = blockIdx.x, b = blockIdx.y;

    const float4* xb = (const float4*)(g_att + (((size_t)b * DIMC) << 14) + (row << 7));
    #pragma unroll
    for (int it = 0; it < 12; ++it) {
        int idx = tid + it * 256;
        int c = idx >> 5, p4 = idx & 31;
        float4 v = xb[(size_t)c * 4096 + p4];
        int px0 = p4 * 4;
        xs[(px0 + 0) * XSTR + c] = __float2half(v.x);
        xs[(px0 + 1) * XSTR + c] = __float2half(v.y);
        xs[(px0 + 2) * XSTR + c] = __float2half(v.z);
        xs[(px0 + 3) * XSTR + c] = __float2half(v.w);
    }
    __syncthreads();

    const int pr = wid * 16 + (lane >> 2);
    const int c0 = (lane & 3) * 2;
    uint32_t A[6][4];
    #pragma unroll
    for (int ks = 0; ks < 6; ++ks) {
        int kb = ks * 16 + c0;
        A[ks][0] = *(const uint32_t*)&xs[pr * XSTR + kb];
        A[ks][1] = *(const uint32_t*)&xs[(pr + 8) * XSTR + kb];
        A[ks][2] = *(const uint32_t*)&xs[pr * XSTR + kb + 8];
        A[ks][3] = *(const uint32_t*)&xs[(pr + 8) * XSTR + kb + 8];
    }

    for (int nt = 0; nt < 12; ++nt) {
        uint2 bf[6];
        #pragma unroll
        for (int ks = 0; ks < 6; ++ks) bf[ks] = g_wproj[(nt * 6 + ks) * 32 + lane];
        float acc[4] = {0.f, 0.f, 0.f, 0.f};
        #pragma unroll
        for (int ks = 0; ks < 6; ++ks) mma_f16_16n8k16(acc, A[ks], bf[ks].x, bf[ks].y);

        int oc = nt * 8 + ((lane & 3) << 1);
        float b0 = bias[oc], b1 = bias[oc + 1];
        float* ob = out + ((((size_t)b * DIMC) + oc) << 14) + (row << 7);
        #pragma unroll
        for (int i = 0; i < 2; ++i) {
            int px = pr + i * 8;
            ob[px]             = acc[2 * i] + b0;
            ob[(1 << 14) + px] = acc[2 * i + 1] + b1;
        }
    }
}

// ---------------- launch ---------------------------------------------------
extern "C" void kernel_launch(void* const* d_in, const int* in_sizes, int n_in,
                              void* d_out, int out_size) {
    const float* x      = (const float*)d_in[0];
    const float* qkv_w  = (const float*)d_in[1];
    const float* qkv_b  = (const float*)d_in[2];
    const float* attn_w = (const float*)d_in[3];
    const float* attn_b = (const float*)d_in[4];
    const float* proj_w = (const float*)d_in[5];
    const float* proj_b = (const float*)d_in[6];
    float* out = (float*)d_out;

    cudaFuncSetAttribute(k1_qkv,  cudaFuncAttributeMaxDynamicSharedMemorySize, SMEM_G);
    cudaFuncSetAttribute(k2_attn, cudaFuncAttributeMaxDynamicSharedMemorySize, SMEM_K2);
    cudaFuncSetAttribute(k3_proj, cudaFuncAttributeMaxDynamicSharedMemorySize, SMEM_G);

    const int k0n = WSQ * BTAPU2 + NQKVF + NPROJF;
    k0_prep<<<(k0n + 255) / 256, 256>>>(attn_w, qkv_w, proj_w);
    k1_qkv<<<dim3(128, BATCH), 256, SMEM_G>>>(x, qkv_b);
    k2_attn<<<dim3(4, 16, NBH), 256, SMEM_K2>>>(attn_b);
    k3_proj<<<dim3(128, BATCH), 256, SMEM_G>>>(proj_b, out);
}